// round 1
// baseline (speedup 1.0000x reference)
#include <cuda_runtime.h>
#include <cstdint>

#define B_ 4
#define N_ 50000
#define E_ 800000
#define C_ 128
#define NOISE_ 100
#define NL_ 5
#define MTOT 200000
#define STATS_G 512
#define GEMM_BLOCKS 1563  /* ceil(200000/128) */

// ---------------- device heap (no allocations allowed) ----------------
#define SZ 25600000L                       // B*N*C floats
#define OFF_X0 0L
#define OFF_X1 SZ
#define OFF_X2 (2L*SZ)
#define OFF_LX (3L*SZ)
#define OFF_VALS (4L*SZ)                   // sorted vals, B*E
#define OFF_PART (OFF_VALS + (long)B_*E_)  // STATS_G*2*2*C
#define OFF_WP (OFF_PART + (long)STATS_G*2*2*C_)
#define OFF_BP (OFF_WP + 256L*C_)
#define HEAP_F (OFF_BP + 128L)

#define OFFI_CNT 0
#define OFFI_RP  (B_*N_)                   // B*(N+1)
#define OFFI_COLS (OFFI_RP + B_*(N_+1))
#define IHEAP (OFFI_COLS + B_*E_)

__device__ __align__(256) float g_heap[HEAP_F];
__device__ __align__(256) int   g_iheap[IHEAP];

// ---------------- helpers ----------------
__device__ __forceinline__ float eluf(float x) {
    return x > 0.f ? x : (__expf(x) - 1.f);
}
__device__ __forceinline__ unsigned long long pk2(float x) {
    unsigned long long r; unsigned int u = __float_as_uint(x);
    asm("mov.b64 %0, {%1, %1};" : "=l"(r) : "r"(u));
    return r;
}
__device__ __forceinline__ void fma2(unsigned long long& d, unsigned long long a, unsigned long long b) {
    asm("fma.rn.f32x2 %0, %1, %2, %0;" : "+l"(d) : "l"(a), "l"(b));
}
__device__ __forceinline__ void upk2(unsigned long long v, float& lo, float& hi) {
    unsigned int a, b;
    asm("mov.b64 {%0, %1}, %2;" : "=r"(a), "=r"(b) : "l"(v));
    lo = __uint_as_float(a); hi = __uint_as_float(b);
}

// ---------------- CSR build ----------------
__global__ void k_zero_cnt() {
    int i = blockIdx.x * 256 + threadIdx.x;
    if (i < B_ * N_) g_iheap[OFFI_CNT + i] = 0;
}

__global__ void k_hist(const int* __restrict__ rows) {
    int i = blockIdx.x * 256 + threadIdx.x;
    if (i < B_ * E_) {
        int b = i / E_;
        atomicAdd(&g_iheap[OFFI_CNT + b * N_ + rows[i]], 1);
    }
}

__global__ void k_scan() {  // grid = B_, block = 1024
    int b = blockIdx.x;
    int* cnt = g_iheap + OFFI_CNT + b * N_;
    int* rp  = g_iheap + OFFI_RP  + b * (N_ + 1);
    __shared__ int s[1024];
    __shared__ int carry;
    if (threadIdx.x == 0) { carry = 0; rp[0] = 0; }
    __syncthreads();
    for (int base = 0; base < N_; base += 1024) {
        int i = base + threadIdx.x;
        int v = (i < N_) ? cnt[i] : 0;
        s[threadIdx.x] = v;
        __syncthreads();
        for (int off = 1; off < 1024; off <<= 1) {
            int t = (threadIdx.x >= off) ? s[threadIdx.x - off] : 0;
            __syncthreads();
            s[threadIdx.x] += t;
            __syncthreads();
        }
        if (i < N_) { rp[i + 1] = carry + s[threadIdx.x]; cnt[i] = 0; }
        __syncthreads();
        if (threadIdx.x == 1023) carry += s[1023];
        __syncthreads();
    }
}

__global__ void k_scatter(const int* __restrict__ rows, const int* __restrict__ colsIn,
                          const float* __restrict__ valsIn) {
    int i = blockIdx.x * 256 + threadIdx.x;
    if (i >= B_ * E_) return;
    int b = i / E_;
    int r = rows[i];
    int pos = g_iheap[OFFI_RP + b * (N_ + 1) + r] + atomicAdd(&g_iheap[OFFI_CNT + b * N_ + r], 1);
    g_iheap[OFFI_COLS + b * E_ + pos] = colsIn[i];
    g_heap[OFF_VALS + (long)b * E_ + pos] = valsIn[i];
}

// ---------------- input projection small term ----------------
__global__ void k_proj(const float* __restrict__ inp, const float* __restrict__ Win,
                       const float* __restrict__ bin, const float* __restrict__ bno, long ooff) {
    long i = (long)blockIdx.x * 256 + threadIdx.x;
    if (i >= (long)MTOT * C_) return;
    int c = (int)(i & 127);
    long r = i >> 7;
    const float* p = inp + r * 3;
    float v = bin[c] + bno[c] + p[0] * Win[c] + p[1] * Win[C_ + c] + p[2] * Win[2 * C_ + c];
    g_heap[ooff + i] = v;
}

// ---------------- Laplacian gather (CSR, warp per row) ----------------
__global__ void k_lap(long xoff, long lxoff) {
    const float* x = g_heap + xoff;
    float* lx = g_heap + lxoff;
    int warp = (blockIdx.x * blockDim.x + threadIdx.x) >> 5;
    int lane = threadIdx.x & 31;
    if (warp >= MTOT) return;
    int b = warp / N_;
    int rr = warp - b * N_;
    const int* rp = g_iheap + OFFI_RP + b * (N_ + 1);
    const int* cols = g_iheap + OFFI_COLS + b * E_;
    const float* vals = g_heap + OFF_VALS + (long)b * E_;
    int e0 = rp[rr], e1 = rp[rr + 1];
    const float* xb = x + (size_t)b * N_ * C_;
    float4 acc = make_float4(0.f, 0.f, 0.f, 0.f);
    int c4 = lane * 4;
    for (int e = e0; e < e1; e += 32) {
        int idx = e + lane;
        int cc = 0; float vv = 0.f;
        if (idx < e1) { cc = cols[idx]; vv = vals[idx]; }
        int mE = min(32, e1 - e);
        for (int t = 0; t < mE; ++t) {
            int c = __shfl_sync(0xffffffffu, cc, t);
            float v = __shfl_sync(0xffffffffu, vv, t);
            float4 xv = *reinterpret_cast<const float4*>(&xb[(size_t)c * C_ + c4]);
            acc.x += v * eluf(xv.x);
            acc.y += v * eluf(xv.y);
            acc.z += v * eluf(xv.z);
            acc.w += v * eluf(xv.w);
        }
    }
    *reinterpret_cast<float4*>(&lx[(size_t)warp * C_ + c4]) = acc;
}

// ---------------- BN stats: deterministic fixed-grid partials ----------------
// A gets elu applied; B (lx) does not. hasB=0 -> half-1 partials are zeros.
__global__ void k_stats(long aoff, long boff, int hasB) {
    const float* A = g_heap + aoff;
    const float* Bv = g_heap + boff;
    int half = threadIdx.x >> 7;
    int c = threadIdx.x & 127;
    float s = 0.f, q = 0.f;
    if (half == 0 || hasB) {
        const float* src = half ? Bv : A;
        for (int r = blockIdx.x; r < MTOT; r += STATS_G) {
            float v = src[(size_t)r * C_ + c];
            if (half == 0) v = eluf(v);
            s += v; q += v * v;
        }
    }
    long base = OFF_PART + ((long)(blockIdx.x * 2 + half) * 2) * C_;
    g_heap[base + c] = s;
    g_heap[base + C_ + c] = q;
}

// ---------------- fold BN into weights: Wp = s.*W, bp = b + (beta - m*s)@W ----
__global__ void k_prep(const float* __restrict__ gamma, const float* __restrict__ beta,
                       const float* __restrict__ Wraw, const float* __restrict__ braw, int K) {
    __shared__ float ss[256], tt[256];
    int k = threadIdx.x;
    if (k < K) {
        float s = 0.f, q = 0.f;
        int c = k & 127;
        int half = k >> 7;
        for (int g = 0; g < STATS_G; ++g) {
            long base = OFF_PART + ((long)(g * 2 + half) * 2) * C_;
            s += g_heap[base + c];
            q += g_heap[base + C_ + c];
        }
        float inv = 1.f / (float)MTOT;
        float mean = s * inv;
        float var = q * inv - mean * mean;
        float sc = gamma[k] * rsqrtf(var + 1e-5f);
        ss[k] = sc;
        tt[k] = beta[k] - mean * sc;
    }
    __syncthreads();
    float* Wp = g_heap + OFF_WP;
    for (int idx = threadIdx.x; idx < K * C_; idx += 256) {
        int kk = idx >> 7;
        Wp[idx] = ss[kk] * Wraw[idx];
    }
    if (threadIdx.x < C_) {
        int c = threadIdx.x;
        float acc = braw[c];
        for (int kk = 0; kk < K; ++kk) acc += tt[kk] * Wraw[kk * C_ + c];
        g_heap[OFF_BP + c] = acc;
    }
}

// ---------------- SGEMM: out[M,128] = [eluA0(A0) | A1] @ W + bias (+resid) ----
// 128x128 block tile, K chunk 32, 8x8 micro-tile, packed f32x2 FMAs.
__global__ void __launch_bounds__(256, 2) k_sgemm(
    const float* __restrict__ Aext, long aoff, int lda, int eluA,
    long a1off, int ksplit,
    const float* __restrict__ Wext, long woff,
    long boff, long roff, long ooff, int K)
{
    const float* A0 = Aext ? Aext : g_heap + aoff;
    const float* A1 = (a1off >= 0) ? g_heap + a1off : (const float*)0;
    const float* W  = Wext ? Wext : g_heap + woff;
    const float* bias  = (boff >= 0) ? g_heap + boff : (const float*)0;
    const float* resid = (roff >= 0) ? g_heap + roff : (const float*)0;
    float* out = g_heap + ooff;

    __shared__ float As[128][33];
    __shared__ float Ws[32][128];

    int tid = threadIdx.x;
    int tx = tid & 15, ty = tid >> 4;
    int rowBase = blockIdx.x * 128;
    int c0 = tx * 8;
    int r0 = ty * 8;

    unsigned long long acc[8][4];
#pragma unroll
    for (int i = 0; i < 8; i++)
#pragma unroll
        for (int j = 0; j < 4; j++) acc[i][j] = 0ull;

    int nChunks = (K + 31) >> 5;
    for (int ch = 0; ch < nChunks; ++ch) {
        int k0 = ch << 5;
        // A tile: 128 rows x 32 k
#pragma unroll
        for (int it = 0; it < 4; ++it) {
            int q = tid + it * 256;
            int row = q >> 3;
            int kq = (q & 7) << 2;
            int grow = rowBase + row;
#pragma unroll
            for (int i = 0; i < 4; ++i) {
                int kg = k0 + kq + i;
                float v = 0.f;
                if (grow < MTOT && kg < K) {
                    if (kg < ksplit) {
                        v = A0[(long)grow * lda + kg];
                        if (eluA) v = eluf(v);
                    } else {
                        v = A1[(long)grow * C_ + (kg - ksplit)];
                    }
                }
                As[row][kq + i] = v;
            }
        }
        // W tile: 32 k x 128 c
#pragma unroll
        for (int it = 0; it < 4; ++it) {
            int q = tid + it * 256;
            int kk = q >> 5;
            int cc = (q & 31) << 2;
            int kg = k0 + kk;
            float4 wv = make_float4(0.f, 0.f, 0.f, 0.f);
            if (kg < K) wv = *reinterpret_cast<const float4*>(&W[(long)kg * C_ + cc]);
            *reinterpret_cast<float4*>(&Ws[kk][cc]) = wv;
        }
        __syncthreads();
#pragma unroll
        for (int k = 0; k < 32; ++k) {
            unsigned long long bb[4];
            const ulonglong2* wp = reinterpret_cast<const ulonglong2*>(&Ws[k][c0]);
            ulonglong2 w0 = wp[0], w1 = wp[1];
            bb[0] = w0.x; bb[1] = w0.y; bb[2] = w1.x; bb[3] = w1.y;
#pragma unroll
            for (int i = 0; i < 8; ++i) {
                unsigned long long a2 = pk2(As[r0 + i][k]);
                fma2(acc[i][0], a2, bb[0]);
                fma2(acc[i][1], a2, bb[1]);
                fma2(acc[i][2], a2, bb[2]);
                fma2(acc[i][3], a2, bb[3]);
            }
        }
        __syncthreads();
    }
    float bv[8];
#pragma unroll
    for (int j = 0; j < 8; j++) bv[j] = bias ? bias[c0 + j] : 0.f;
#pragma unroll
    for (int i = 0; i < 8; i++) {
        int grow = rowBase + r0 + i;
        if (grow >= MTOT) continue;
        float o[8];
#pragma unroll
        for (int j = 0; j < 4; j++) {
            float lo, hi;
            upk2(acc[i][j], lo, hi);
            o[2 * j] = lo + bv[2 * j];
            o[2 * j + 1] = hi + bv[2 * j + 1];
        }
        if (resid) {
#pragma unroll
            for (int j = 0; j < 8; j++) o[j] += resid[(long)grow * C_ + c0 + j];
        }
        float4* op = reinterpret_cast<float4*>(&out[(long)grow * C_ + c0]);
        op[0] = make_float4(o[0], o[1], o[2], o[3]);
        op[1] = make_float4(o[4], o[5], o[6], o[7]);
    }
}

// ---------------- final: mu = elu(h)@W_mu + b_mu + inputs; y = logvar --------
__global__ void k_final(long hoff, const float* __restrict__ inp,
                        const float* __restrict__ Wmu, const float* __restrict__ bmu,
                        const float* __restrict__ logv, float* __restrict__ out) {
    int warp = (blockIdx.x * blockDim.x + threadIdx.x) >> 5;
    int lane = threadIdx.x & 31;
    if (warp >= MTOT) return;
    const float* h = g_heap + hoff + (size_t)warp * C_;
    float4 hv = *reinterpret_cast<const float4*>(&h[lane * 4]);
    float e0 = eluf(hv.x), e1 = eluf(hv.y), e2 = eluf(hv.z), e3 = eluf(hv.w);
    int c0 = lane * 4;
    float p0, p1, p2;
    p0 = e0 * Wmu[c0 * 3 + 0] + e1 * Wmu[(c0 + 1) * 3 + 0] + e2 * Wmu[(c0 + 2) * 3 + 0] + e3 * Wmu[(c0 + 3) * 3 + 0];
    p1 = e0 * Wmu[c0 * 3 + 1] + e1 * Wmu[(c0 + 1) * 3 + 1] + e2 * Wmu[(c0 + 2) * 3 + 1] + e3 * Wmu[(c0 + 3) * 3 + 1];
    p2 = e0 * Wmu[c0 * 3 + 2] + e1 * Wmu[(c0 + 1) * 3 + 2] + e2 * Wmu[(c0 + 2) * 3 + 2] + e3 * Wmu[(c0 + 3) * 3 + 2];
#pragma unroll
    for (int off = 16; off; off >>= 1) {
        p0 += __shfl_xor_sync(0xffffffffu, p0, off);
        p1 += __shfl_xor_sync(0xffffffffu, p1, off);
        p2 += __shfl_xor_sync(0xffffffffu, p2, off);
    }
    if (lane < 3) {
        float pv = (lane == 0) ? p0 : ((lane == 1) ? p1 : p2);
        float mu = pv + bmu[lane] + inp[(size_t)warp * 3 + lane];
        out[(size_t)warp * 3 + lane] = mu;
        out[(size_t)MTOT * 3 + (size_t)warp * 3 + lane] = logv[0];
    }
}

// ---------------- host orchestration ----------------
static long off_x(int i) { return (long)i * SZ; }

extern "C" void kernel_launch(void* const* d_in, const int* in_sizes, int n_in,
                              void* d_out, int out_size) {
    const float* inputs = (const float*)d_in[0];
    const float* noise  = (const float*)d_in[1];
    /* d_in[2] = mask, unused by reference */
    const int*   Lr = (const int*)d_in[3];
    const int*   Lc = (const int*)d_in[4];
    const float* Lv = (const float*)d_in[5];
    const float* W_in = (const float*)d_in[6];
    const float* b_in = (const float*)d_in[7];
    const float* W_no = (const float*)d_in[8];
    const float* b_no = (const float*)d_in[9];
    const float* rng  = (const float*)d_in[10];
    const float* rnb  = (const float*)d_in[11];
    const float* rnW  = (const float*)d_in[12];
    const float* rnbs = (const float*)d_in[13];
    const float* g2   = (const float*)d_in[14];
    const float* be2  = (const float*)d_in[15];
    const float* W2   = (const float*)d_in[16];
    const float* b2   = (const float*)d_in[17];
    const float* Wmu  = (const float*)d_in[18];
    const float* bmu  = (const float*)d_in[19];
    const float* logv = (const float*)d_in[20];
    float* out = (float*)d_out;

    // CSR build (L is reused by all 10 lap applications)
    k_zero_cnt<<<(B_ * N_ + 255) / 256, 256>>>();
    k_hist<<<(B_ * E_ + 255) / 256, 256>>>(Lr);
    k_scan<<<B_, 1024>>>();
    k_scatter<<<(B_ * E_ + 255) / 256, 256>>>(Lr, Lc, Lv);

    // input projection: LX <- b_in+b_noise+inputs@W_in ; X0 <- noise@W_noise + LX
    k_proj<<<(int)(((long)MTOT * C_ + 255) / 256), 256>>>(inputs, W_in, b_in, b_no, OFF_LX);
    k_sgemm<<<GEMM_BLOCKS, 256>>>(noise, 0, NOISE_, 0, -1L, NOISE_,
                                  W_no, 0, -1L, OFF_LX, off_x(0), NOISE_);

    int p = 0;
    for (int i = 0; i < NL_; ++i) {
        int cur = p, mid = (p + 1) % 3, nxt = (p + 2) % 3;
        // block j = 0
        k_lap<<<MTOT / 8, 256>>>(off_x(cur), OFF_LX);
        k_stats<<<STATS_G, 256>>>(off_x(cur), OFF_LX, 1);
        k_prep<<<1, 256>>>(rng + (long)(i * 2 + 0) * 256, rnb + (long)(i * 2 + 0) * 256,
                           rnW + (long)(i * 2 + 0) * 256 * 128, rnbs + (long)(i * 2 + 0) * 128, 256);
        k_sgemm<<<GEMM_BLOCKS, 256>>>((const float*)0, off_x(cur), C_, 1, OFF_LX, C_,
                                      (const float*)0, OFF_WP, OFF_BP, -1L, off_x(mid), 2 * C_);
        // block j = 1 (+ residual from layer input)
        k_lap<<<MTOT / 8, 256>>>(off_x(mid), OFF_LX);
        k_stats<<<STATS_G, 256>>>(off_x(mid), OFF_LX, 1);
        k_prep<<<1, 256>>>(rng + (long)(i * 2 + 1) * 256, rnb + (long)(i * 2 + 1) * 256,
                           rnW + (long)(i * 2 + 1) * 256 * 128, rnbs + (long)(i * 2 + 1) * 128, 256);
        k_sgemm<<<GEMM_BLOCKS, 256>>>((const float*)0, off_x(mid), C_, 1, OFF_LX, C_,
                                      (const float*)0, OFF_WP, OFF_BP, off_x(cur), off_x(nxt), 2 * C_);
        p = nxt;
    }

    // final head: h = elu(x)@fold(W2) + b2' ; out = elu(h)@W_mu + b_mu + inputs ; y = logvar
    k_stats<<<STATS_G, 256>>>(off_x(p), 0, 0);
    k_prep<<<1, 256>>>(g2, be2, W2, b2, 128);
    int hb = (p + 1) % 3;
    k_sgemm<<<GEMM_BLOCKS, 256>>>((const float*)0, off_x(p), C_, 1, -1L, C_,
                                  (const float*)0, OFF_WP, OFF_BP, -1L, off_x(hb), C_);
    k_final<<<MTOT / 8, 256>>>(off_x(hb), inputs, Wmu, bmu, logv, out);
}

// round 2
// speedup vs baseline: 1.0001x; 1.0001x over previous
#include <cuda_runtime.h>
#include <cstdint>

#define B_ 4
#define N_ 50000
#define E_ 800000
#define C_ 128
#define NOISE_ 100
#define NL_ 5
#define MTOT 200000
#define STATS_G 512
#define GEMM_BLOCKS 1563  /* ceil(200000/128) */

// ---------------- device heap (no allocations allowed) ----------------
#define SZ 25600000L                       // B*N*C floats
#define OFF_X0 0L
#define OFF_X1 SZ
#define OFF_X2 (2L*SZ)
#define OFF_LX (3L*SZ)
#define OFF_VALS (4L*SZ)                   // sorted vals, B*E
#define OFF_PART (OFF_VALS + (long)B_*E_)  // STATS_G*2*2*C
#define OFF_WP (OFF_PART + (long)STATS_G*2*2*C_)
#define OFF_BP (OFF_WP + 256L*C_)
#define HEAP_F (OFF_BP + 128L)

#define OFFI_CNT 0
#define OFFI_RP  (B_*N_)                   // B*(N+1)
#define OFFI_COLS (OFFI_RP + B_*(N_+1))
#define IHEAP (OFFI_COLS + B_*E_)

__device__ __align__(256) float g_heap[HEAP_F];
__device__ __align__(256) int   g_iheap[IHEAP];

// ---------------- helpers ----------------
__device__ __forceinline__ float eluf(float x) {
    return x > 0.f ? x : (__expf(x) - 1.f);
}
__device__ __forceinline__ unsigned long long pk2(float x) {
    unsigned long long r; unsigned int u = __float_as_uint(x);
    asm("mov.b64 %0, {%1, %1};" : "=l"(r) : "r"(u));
    return r;
}
__device__ __forceinline__ void fma2(unsigned long long& d, unsigned long long a, unsigned long long b) {
    asm("fma.rn.f32x2 %0, %1, %2, %0;" : "+l"(d) : "l"(a), "l"(b));
}
__device__ __forceinline__ void upk2(unsigned long long v, float& lo, float& hi) {
    unsigned int a, b;
    asm("mov.b64 {%0, %1}, %2;" : "=r"(a), "=r"(b) : "l"(v));
    lo = __uint_as_float(a); hi = __uint_as_float(b);
}

// ---------------- CSR build ----------------
__global__ void k_zero_cnt() {
    int i = blockIdx.x * 256 + threadIdx.x;
    if (i < B_ * N_) g_iheap[OFFI_CNT + i] = 0;
}

__global__ void k_hist(const int* __restrict__ rows) {
    int i = blockIdx.x * 256 + threadIdx.x;
    if (i < B_ * E_) {
        int b = i / E_;
        atomicAdd(&g_iheap[OFFI_CNT + b * N_ + rows[i]], 1);
    }
}

__global__ void k_scan() {  // grid = B_, block = 1024
    int b = blockIdx.x;
    int* cnt = g_iheap + OFFI_CNT + b * N_;
    int* rp  = g_iheap + OFFI_RP  + b * (N_ + 1);
    __shared__ int s[1024];
    __shared__ int carry;
    if (threadIdx.x == 0) { carry = 0; rp[0] = 0; }
    __syncthreads();
    for (int base = 0; base < N_; base += 1024) {
        int i = base + threadIdx.x;
        int v = (i < N_) ? cnt[i] : 0;
        s[threadIdx.x] = v;
        __syncthreads();
        for (int off = 1; off < 1024; off <<= 1) {
            int t = (threadIdx.x >= off) ? s[threadIdx.x - off] : 0;
            __syncthreads();
            s[threadIdx.x] += t;
            __syncthreads();
        }
        if (i < N_) { rp[i + 1] = carry + s[threadIdx.x]; cnt[i] = 0; }
        __syncthreads();
        if (threadIdx.x == 1023) carry += s[1023];
        __syncthreads();
    }
}

__global__ void k_scatter(const int* __restrict__ rows, const int* __restrict__ colsIn,
                          const float* __restrict__ valsIn) {
    int i = blockIdx.x * 256 + threadIdx.x;
    if (i >= B_ * E_) return;
    int b = i / E_;
    int r = rows[i];
    int pos = g_iheap[OFFI_RP + b * (N_ + 1) + r] + atomicAdd(&g_iheap[OFFI_CNT + b * N_ + r], 1);
    g_iheap[OFFI_COLS + b * E_ + pos] = colsIn[i];
    g_heap[OFF_VALS + (long)b * E_ + pos] = valsIn[i];
}

// ---------------- input projection small term ----------------
__global__ void k_proj(const float* __restrict__ inp, const float* __restrict__ Win,
                       const float* __restrict__ bin, const float* __restrict__ bno, long ooff) {
    long i = (long)blockIdx.x * 256 + threadIdx.x;
    if (i >= (long)MTOT * C_) return;
    int c = (int)(i & 127);
    long r = i >> 7;
    const float* p = inp + r * 3;
    float v = bin[c] + bno[c] + p[0] * Win[c] + p[1] * Win[C_ + c] + p[2] * Win[2 * C_ + c];
    g_heap[ooff + i] = v;
}

// ---------------- Laplacian gather (CSR, warp per row) ----------------
__global__ void k_lap(long xoff, long lxoff) {
    const float* x = g_heap + xoff;
    float* lx = g_heap + lxoff;
    int warp = (blockIdx.x * blockDim.x + threadIdx.x) >> 5;
    int lane = threadIdx.x & 31;
    if (warp >= MTOT) return;
    int b = warp / N_;
    int rr = warp - b * N_;
    const int* rp = g_iheap + OFFI_RP + b * (N_ + 1);
    const int* cols = g_iheap + OFFI_COLS + b * E_;
    const float* vals = g_heap + OFF_VALS + (long)b * E_;
    int e0 = rp[rr], e1 = rp[rr + 1];
    const float* xb = x + (size_t)b * N_ * C_;
    float4 acc = make_float4(0.f, 0.f, 0.f, 0.f);
    int c4 = lane * 4;
    for (int e = e0; e < e1; e += 32) {
        int idx = e + lane;
        int cc = 0; float vv = 0.f;
        if (idx < e1) { cc = cols[idx]; vv = vals[idx]; }
        int mE = min(32, e1 - e);
        for (int t = 0; t < mE; ++t) {
            int c = __shfl_sync(0xffffffffu, cc, t);
            float v = __shfl_sync(0xffffffffu, vv, t);
            float4 xv = *reinterpret_cast<const float4*>(&xb[(size_t)c * C_ + c4]);
            acc.x += v * eluf(xv.x);
            acc.y += v * eluf(xv.y);
            acc.z += v * eluf(xv.z);
            acc.w += v * eluf(xv.w);
        }
    }
    *reinterpret_cast<float4*>(&lx[(size_t)warp * C_ + c4]) = acc;
}

// ---------------- BN stats: deterministic fixed-grid partials ----------------
// A gets elu applied; B (lx) does not. hasB=0 -> half-1 partials are zeros.
__global__ void k_stats(long aoff, long boff, int hasB) {
    const float* A = g_heap + aoff;
    const float* Bv = g_heap + boff;
    int half = threadIdx.x >> 7;
    int c = threadIdx.x & 127;
    float s = 0.f, q = 0.f;
    if (half == 0 || hasB) {
        const float* src = half ? Bv : A;
        for (int r = blockIdx.x; r < MTOT; r += STATS_G) {
            float v = src[(size_t)r * C_ + c];
            if (half == 0) v = eluf(v);
            s += v; q += v * v;
        }
    }
    long base = OFF_PART + ((long)(blockIdx.x * 2 + half) * 2) * C_;
    g_heap[base + c] = s;
    g_heap[base + C_ + c] = q;
}

// ---------------- fold BN into weights: Wp = s.*W, bp = b + (beta - m*s)@W ----
__global__ void k_prep(const float* __restrict__ gamma, const float* __restrict__ beta,
                       const float* __restrict__ Wraw, const float* __restrict__ braw, int K) {
    __shared__ float ss[256], tt[256];
    int k = threadIdx.x;
    if (k < K) {
        float s = 0.f, q = 0.f;
        int c = k & 127;
        int half = k >> 7;
        for (int g = 0; g < STATS_G; ++g) {
            long base = OFF_PART + ((long)(g * 2 + half) * 2) * C_;
            s += g_heap[base + c];
            q += g_heap[base + C_ + c];
        }
        float inv = 1.f / (float)MTOT;
        float mean = s * inv;
        float var = q * inv - mean * mean;
        float sc = gamma[k] * rsqrtf(var + 1e-5f);
        ss[k] = sc;
        tt[k] = beta[k] - mean * sc;
    }
    __syncthreads();
    float* Wp = g_heap + OFF_WP;
    for (int idx = threadIdx.x; idx < K * C_; idx += 256) {
        int kk = idx >> 7;
        Wp[idx] = ss[kk] * Wraw[idx];
    }
    if (threadIdx.x < C_) {
        int c = threadIdx.x;
        float acc = braw[c];
        for (int kk = 0; kk < K; ++kk) acc += tt[kk] * Wraw[kk * C_ + c];
        g_heap[OFF_BP + c] = acc;
    }
}

// ---------------- SGEMM: out[M,128] = [eluA0(A0) | A1] @ W + bias (+resid) ----
// 128x128 block tile, K chunk 32, 8x8 micro-tile, packed f32x2 FMAs.
__global__ void __launch_bounds__(256, 2) k_sgemm(
    const float* __restrict__ Aext, long aoff, int lda, int eluA,
    long a1off, int ksplit,
    const float* __restrict__ Wext, long woff,
    long boff, long roff, long ooff, int K)
{
    const float* A0 = Aext ? Aext : g_heap + aoff;
    const float* A1 = (a1off >= 0) ? g_heap + a1off : (const float*)0;
    const float* W  = Wext ? Wext : g_heap + woff;
    const float* bias  = (boff >= 0) ? g_heap + boff : (const float*)0;
    const float* resid = (roff >= 0) ? g_heap + roff : (const float*)0;
    float* out = g_heap + ooff;

    __shared__ float As[128][33];
    __shared__ float Ws[32][128];

    int tid = threadIdx.x;
    int tx = tid & 15, ty = tid >> 4;
    int rowBase = blockIdx.x * 128;
    int c0 = tx * 8;
    int r0 = ty * 8;

    unsigned long long acc[8][4];
#pragma unroll
    for (int i = 0; i < 8; i++)
#pragma unroll
        for (int j = 0; j < 4; j++) acc[i][j] = 0ull;

    int nChunks = (K + 31) >> 5;
    for (int ch = 0; ch < nChunks; ++ch) {
        int k0 = ch << 5;
        // A tile: 128 rows x 32 k
#pragma unroll
        for (int it = 0; it < 4; ++it) {
            int q = tid + it * 256;
            int row = q >> 3;
            int kq = (q & 7) << 2;
            int grow = rowBase + row;
#pragma unroll
            for (int i = 0; i < 4; ++i) {
                int kg = k0 + kq + i;
                float v = 0.f;
                if (grow < MTOT && kg < K) {
                    if (kg < ksplit) {
                        v = A0[(long)grow * lda + kg];
                        if (eluA) v = eluf(v);
                    } else {
                        v = A1[(long)grow * C_ + (kg - ksplit)];
                    }
                }
                As[row][kq + i] = v;
            }
        }
        // W tile: 32 k x 128 c
#pragma unroll
        for (int it = 0; it < 4; ++it) {
            int q = tid + it * 256;
            int kk = q >> 5;
            int cc = (q & 31) << 2;
            int kg = k0 + kk;
            float4 wv = make_float4(0.f, 0.f, 0.f, 0.f);
            if (kg < K) wv = *reinterpret_cast<const float4*>(&W[(long)kg * C_ + cc]);
            *reinterpret_cast<float4*>(&Ws[kk][cc]) = wv;
        }
        __syncthreads();
#pragma unroll
        for (int k = 0; k < 32; ++k) {
            unsigned long long bb[4];
            const ulonglong2* wp = reinterpret_cast<const ulonglong2*>(&Ws[k][c0]);
            ulonglong2 w0 = wp[0], w1 = wp[1];
            bb[0] = w0.x; bb[1] = w0.y; bb[2] = w1.x; bb[3] = w1.y;
#pragma unroll
            for (int i = 0; i < 8; ++i) {
                unsigned long long a2 = pk2(As[r0 + i][k]);
                fma2(acc[i][0], a2, bb[0]);
                fma2(acc[i][1], a2, bb[1]);
                fma2(acc[i][2], a2, bb[2]);
                fma2(acc[i][3], a2, bb[3]);
            }
        }
        __syncthreads();
    }
    float bv[8];
#pragma unroll
    for (int j = 0; j < 8; j++) bv[j] = bias ? bias[c0 + j] : 0.f;
#pragma unroll
    for (int i = 0; i < 8; i++) {
        int grow = rowBase + r0 + i;
        if (grow >= MTOT) continue;
        float o[8];
#pragma unroll
        for (int j = 0; j < 4; j++) {
            float lo, hi;
            upk2(acc[i][j], lo, hi);
            o[2 * j] = lo + bv[2 * j];
            o[2 * j + 1] = hi + bv[2 * j + 1];
        }
        if (resid) {
#pragma unroll
            for (int j = 0; j < 8; j++) o[j] += resid[(long)grow * C_ + c0 + j];
        }
        float4* op = reinterpret_cast<float4*>(&out[(long)grow * C_ + c0]);
        op[0] = make_float4(o[0], o[1], o[2], o[3]);
        op[1] = make_float4(o[4], o[5], o[6], o[7]);
    }
}

// ---------------- final: mu = elu(h)@W_mu + b_mu + inputs; y = logvar --------
__global__ void k_final(long hoff, const float* __restrict__ inp,
                        const float* __restrict__ Wmu, const float* __restrict__ bmu,
                        const float* __restrict__ logv, float* __restrict__ out) {
    int warp = (blockIdx.x * blockDim.x + threadIdx.x) >> 5;
    int lane = threadIdx.x & 31;
    if (warp >= MTOT) return;
    const float* h = g_heap + hoff + (size_t)warp * C_;
    float4 hv = *reinterpret_cast<const float4*>(&h[lane * 4]);
    float e0 = eluf(hv.x), e1 = eluf(hv.y), e2 = eluf(hv.z), e3 = eluf(hv.w);
    int c0 = lane * 4;
    float p0, p1, p2;
    p0 = e0 * Wmu[c0 * 3 + 0] + e1 * Wmu[(c0 + 1) * 3 + 0] + e2 * Wmu[(c0 + 2) * 3 + 0] + e3 * Wmu[(c0 + 3) * 3 + 0];
    p1 = e0 * Wmu[c0 * 3 + 1] + e1 * Wmu[(c0 + 1) * 3 + 1] + e2 * Wmu[(c0 + 2) * 3 + 1] + e3 * Wmu[(c0 + 3) * 3 + 1];
    p2 = e0 * Wmu[c0 * 3 + 2] + e1 * Wmu[(c0 + 1) * 3 + 2] + e2 * Wmu[(c0 + 2) * 3 + 2] + e3 * Wmu[(c0 + 3) * 3 + 2];
#pragma unroll
    for (int off = 16; off; off >>= 1) {
        p0 += __shfl_xor_sync(0xffffffffu, p0, off);
        p1 += __shfl_xor_sync(0xffffffffu, p1, off);
        p2 += __shfl_xor_sync(0xffffffffu, p2, off);
    }
    if (lane < 3) {
        float pv = (lane == 0) ? p0 : ((lane == 1) ? p1 : p2);
        float mu = pv + bmu[lane] + inp[(size_t)warp * 3 + lane];
        out[(size_t)warp * 3 + lane] = mu;
        out[(size_t)MTOT * 3 + (size_t)warp * 3 + lane] = logv[0];
    }
}

// ---------------- host orchestration ----------------
static long off_x(int i) { return (long)i * SZ; }

extern "C" void kernel_launch(void* const* d_in, const int* in_sizes, int n_in,
                              void* d_out, int out_size) {
    const float* inputs = (const float*)d_in[0];
    const float* noise  = (const float*)d_in[1];
    /* d_in[2] = mask, unused by reference */
    const int*   Lr = (const int*)d_in[3];
    const int*   Lc = (const int*)d_in[4];
    const float* Lv = (const float*)d_in[5];
    const float* W_in = (const float*)d_in[6];
    const float* b_in = (const float*)d_in[7];
    const float* W_no = (const float*)d_in[8];
    const float* b_no = (const float*)d_in[9];
    const float* rng  = (const float*)d_in[10];
    const float* rnb  = (const float*)d_in[11];
    const float* rnW  = (const float*)d_in[12];
    const float* rnbs = (const float*)d_in[13];
    const float* g2   = (const float*)d_in[14];
    const float* be2  = (const float*)d_in[15];
    const float* W2   = (const float*)d_in[16];
    const float* b2   = (const float*)d_in[17];
    const float* Wmu  = (const float*)d_in[18];
    const float* bmu  = (const float*)d_in[19];
    const float* logv = (const float*)d_in[20];
    float* out = (float*)d_out;

    // CSR build (L is reused by all 10 lap applications)
    k_zero_cnt<<<(B_ * N_ + 255) / 256, 256>>>();
    k_hist<<<(B_ * E_ + 255) / 256, 256>>>(Lr);
    k_scan<<<B_, 1024>>>();
    k_scatter<<<(B_ * E_ + 255) / 256, 256>>>(Lr, Lc, Lv);

    // input projection: LX <- b_in+b_noise+inputs@W_in ; X0 <- noise@W_noise + LX
    k_proj<<<(int)(((long)MTOT * C_ + 255) / 256), 256>>>(inputs, W_in, b_in, b_no, OFF_LX);
    k_sgemm<<<GEMM_BLOCKS, 256>>>(noise, 0, NOISE_, 0, -1L, NOISE_,
                                  W_no, 0, -1L, OFF_LX, off_x(0), NOISE_);

    int p = 0;
    for (int i = 0; i < NL_; ++i) {
        int cur = p, mid = (p + 1) % 3, nxt = (p + 2) % 3;
        // block j = 0
        k_lap<<<MTOT / 8, 256>>>(off_x(cur), OFF_LX);
        k_stats<<<STATS_G, 256>>>(off_x(cur), OFF_LX, 1);
        k_prep<<<1, 256>>>(rng + (long)(i * 2 + 0) * 256, rnb + (long)(i * 2 + 0) * 256,
                           rnW + (long)(i * 2 + 0) * 256 * 128, rnbs + (long)(i * 2 + 0) * 128, 256);
        k_sgemm<<<GEMM_BLOCKS, 256>>>((const float*)0, off_x(cur), C_, 1, OFF_LX, C_,
                                      (const float*)0, OFF_WP, OFF_BP, -1L, off_x(mid), 2 * C_);
        // block j = 1 (+ residual from layer input)
        k_lap<<<MTOT / 8, 256>>>(off_x(mid), OFF_LX);
        k_stats<<<STATS_G, 256>>>(off_x(mid), OFF_LX, 1);
        k_prep<<<1, 256>>>(rng + (long)(i * 2 + 1) * 256, rnb + (long)(i * 2 + 1) * 256,
                           rnW + (long)(i * 2 + 1) * 256 * 128, rnbs + (long)(i * 2 + 1) * 128, 256);
        k_sgemm<<<GEMM_BLOCKS, 256>>>((const float*)0, off_x(mid), C_, 1, OFF_LX, C_,
                                      (const float*)0, OFF_WP, OFF_BP, off_x(cur), off_x(nxt), 2 * C_);
        p = nxt;
    }

    // final head: h = elu(x)@fold(W2) + b2' ; out = elu(h)@W_mu + b_mu + inputs ; y = logvar
    k_stats<<<STATS_G, 256>>>(off_x(p), 0, 0);
    k_prep<<<1, 256>>>(g2, be2, W2, b2, 128);
    int hb = (p + 1) % 3;
    k_sgemm<<<GEMM_BLOCKS, 256>>>((const float*)0, off_x(p), C_, 1, -1L, C_,
                                  (const float*)0, OFF_WP, OFF_BP, -1L, off_x(hb), C_);
    k_final<<<MTOT / 8, 256>>>(off_x(hb), inputs, Wmu, bmu, logv, out);
}